// round 9
// baseline (speedup 1.0000x reference)
#include <cuda_runtime.h>
#include <cuda_fp16.h>
#include <cstdint>

#define BATCH 2
#define NSEQ  2048
#define CH    768
#define NH    12
#define DH    64
#define WIN   7
#define C3    (3*CH)
#define MTOT  (BATCH*NSEQ)   // 4096
#define KDIM  CH             // 768
#define BK    64
#define NCHUNK (KDIM/BK)     // 12
#define LO_SCALE 2048.0f
#define LO_INV   (1.0f/2048.0f)

// ---------------- scratch (allocation-free) ----------------
__device__ float g_qkv[(size_t)MTOT*C3];
__device__ __half g_x16[(size_t)MTOT*CH];
__device__ __half g_qhi[(size_t)C3*CH],  g_qlo[(size_t)C3*CH];
__device__ __half g_phi[(size_t)CH*CH],  g_plo[(size_t)CH*CH];
__device__ __half g_att[(size_t)MTOT*CH];

// ---------------- helpers ----------------
__device__ __forceinline__ uint32_t smem_u32(const void* p) {
    uint32_t a;
    asm("{ .reg .u64 t; cvta.to.shared.u64 t, %1; cvt.u32.u64 %0, t; }" : "=r"(a) : "l"(p));
    return a;
}
__device__ __forceinline__ void cp16(uint32_t dst, const void* src) {
    asm volatile("cp.async.cg.shared.global [%0], [%1], 16;" :: "r"(dst), "l"(src) : "memory");
}
#define CP_COMMIT() asm volatile("cp.async.commit_group;" ::: "memory")
#define CP_WAIT0()  asm volatile("cp.async.wait_group 0;" ::: "memory")

#define LDSM_X4(r0, r1, r2, r3, addr)                                            \
    asm volatile("ldmatrix.sync.aligned.m8n8.x4.shared.b16 {%0,%1,%2,%3}, [%4];" \
                 : "=r"(r0), "=r"(r1), "=r"(r2), "=r"(r3) : "r"(addr))

// fp32-accum HMMA (hi product)
#define MMA_F32ACC(acc, a, b0, b1)                                            \
    asm("mma.sync.aligned.m16n8k16.row.col.f32.f16.f16.f32 "                  \
        "{%0,%1,%2,%3},{%4,%5,%6,%7},{%8,%9},{%0,%1,%2,%3};"                  \
        : "+f"((acc)[0]), "+f"((acc)[1]), "+f"((acc)[2]), "+f"((acc)[3])      \
        : "r"((a)[0]), "r"((a)[1]), "r"((a)[2]), "r"((a)[3]),                 \
          "r"(b0), "r"(b1))

// fp16-accum HMMA (lo product, pre-scaled)
#define MMA_F16ACC(acc2, a, b0, b1)                                           \
    asm("mma.sync.aligned.m16n8k16.row.col.f16.f16.f16.f16 "                  \
        "{%0,%1},{%2,%3,%4,%5},{%6,%7},{%0,%1};"                              \
        : "+r"((acc2)[0]), "+r"((acc2)[1])                                    \
        : "r"((a)[0]), "r"((a)[1]), "r"((a)[2]), "r"((a)[3]),                 \
          "r"(b0), "r"(b1))

// swizzled offset within rows x 128B tile: full 8-position 16B permutation
__device__ __forceinline__ uint32_t swz(int row, int colb) {
    return (uint32_t)(row * 128 + (colb ^ ((row & 7) << 4)));
}

// ---------------- fused conversions ----------------
#define N4_X  (MTOT*CH/4)
#define N4_Q  (C3*CH/4)
#define N4_P  (CH*CH/4)

__device__ __forceinline__ void conv4(const float* __restrict__ in,
                                      __half* __restrict__ o, int idx)
{
    float4 v = ((const float4*)in)[idx];
    __half2* op = (__half2*)(o + 4 * (size_t)idx);
    op[0] = __floats2half2_rn(v.x, v.y);
    op[1] = __floats2half2_rn(v.z, v.w);
}
// hi = fp16(w); lo = fp16((w - hi) * 2048)
__device__ __forceinline__ void split4(const float* __restrict__ in,
    __half* __restrict__ hi, __half* __restrict__ lo, int idx)
{
    float4 v = ((const float4*)in)[idx];
    __half h0 = __float2half(v.x), h1 = __float2half(v.y);
    __half h2 = __float2half(v.z), h3 = __float2half(v.w);
    __half l0 = __float2half((v.x - __half2float(h0)) * LO_SCALE);
    __half l1 = __float2half((v.y - __half2float(h1)) * LO_SCALE);
    __half l2 = __float2half((v.z - __half2float(h2)) * LO_SCALE);
    __half l3 = __float2half((v.w - __half2float(h3)) * LO_SCALE);
    __half2* hp = (__half2*)(hi + 4 * (size_t)idx);
    __half2* lp = (__half2*)(lo + 4 * (size_t)idx);
    hp[0] = __half2(h0, h1); hp[1] = __half2(h2, h3);
    lp[0] = __half2(l0, l1); lp[1] = __half2(l2, l3);
}

__global__ void __launch_bounds__(256)
split_all(const float* __restrict__ x, const float* __restrict__ wq,
          const float* __restrict__ wp,
          __half* __restrict__ x16,
          __half* __restrict__ qhi, __half* __restrict__ qlo,
          __half* __restrict__ phi, __half* __restrict__ plo)
{
    int idx = blockIdx.x * blockDim.x + threadIdx.x;
    if (idx < N4_X)                    conv4(x, x16, idx);
    else if (idx < N4_X + N4_Q)        split4(wq, qhi, qlo, idx - N4_X);
    else if (idx < N4_X + N4_Q + N4_P) split4(wp, phi, plo, idx - N4_X - N4_Q);
}

// ---------------- HMMA GEMM: hi fp32-accum + lo fp16-accum (scaled) ----------------
// Stage layout: [A BM*128][Whi BN*128][Wlo BN*128]
template<int BM_, int BN_>
__global__ void __launch_bounds__(256, 2)
gemm2(const __half* __restrict__ A, const __half* __restrict__ Whi,
      const __half* __restrict__ Wlo,
      const float* __restrict__ bias, float* __restrict__ C, int N)
{
    constexpr int MT     = BM_ / 32;       // m16 tiles per warp (warp covers BM/2 rows)
    constexpr int NTT    = BN_ / 32;       // n8 tiles per warp (warp covers BN/4 cols)
    constexpr int BT     = NTT / 2;        // 16-row B LDSM groups per warp
    constexpr int ATILE  = BM_ * 128;
    constexpr int WTILE  = BN_ * 128;
    constexpr int STAGEB = ATILE + 2 * WTILE;

    extern __shared__ char smem[];
    const uint32_t sb = smem_u32(smem);
    const int tid = threadIdx.x, wid = tid >> 5, lane = tid & 31;
    const int m0 = blockIdx.y * BM_, n0 = blockIdx.x * BN_;
    const int wm = (wid >> 2) * (BM_ / 2);     // 2 warp rows
    const int wn = (wid & 3) * (BN_ / 4);      // 4 warp cols

    const char* pA  = (const char*)A;
    const char* pWh = (const char*)Whi;
    const char* pWl = (const char*)Wlo;

    float    accf[MT][NTT][4];
    uint32_t acch[MT][NTT][2];
    #pragma unroll
    for (int i = 0; i < MT; i++)
        #pragma unroll
        for (int j = 0; j < NTT; j++) {
            #pragma unroll
            for (int t = 0; t < 4; t++) accf[i][j][t] = 0.f;
            acch[i][j][0] = 0u; acch[i][j][1] = 0u;
        }

    auto fill_stage = [&](uint32_t stb, int k0) {
        #pragma unroll
        for (int s = tid; s < BM_ * 8; s += 256) {
            int row = s >> 3, ks = s & 7;
            uint32_t so = swz(row, ks * 16);
            size_t ga = ((size_t)(m0 + row) * KDIM + k0 + ks * 8) * 2;
            cp16(stb + so, pA + ga);
        }
        #pragma unroll
        for (int s = tid; s < BN_ * 8; s += 256) {
            int row = s >> 3, ks = s & 7;
            uint32_t so = swz(row, ks * 16);
            size_t gw = ((size_t)(n0 + row) * KDIM + k0 + ks * 8) * 2;
            cp16(stb + ATILE + so,         pWh + gw);
            cp16(stb + ATILE + WTILE + so, pWl + gw);
        }
    };

    // prologue
    fill_stage(sb, 0);
    CP_COMMIT();

    const int r = lane & 15, cg = lane >> 4;

    #pragma unroll 1
    for (int c = 0; c < NCHUNK; c++) {
        const uint32_t stb = sb + (c & 1) * STAGEB;

        CP_WAIT0();
        __syncthreads();

        if (c + 1 < NCHUNK)
            fill_stage(sb + ((c + 1) & 1) * STAGEB, (c + 1) * BK);
        CP_COMMIT();

        #pragma unroll
        for (int kstep = 0; kstep < 4; kstep++) {
            const int kb = kstep * 32;
            uint32_t av[MT][4], bf[BT][4];
            #pragma unroll
            for (int mt = 0; mt < MT; mt++) {
                uint32_t ad = stb + swz(wm + mt * 16 + r, kb + cg * 16);
                LDSM_X4(av[mt][0], av[mt][1], av[mt][2], av[mt][3], ad);
            }
            // hi product: fp32 accum
            #pragma unroll
            for (int bt = 0; bt < BT; bt++) {
                uint32_t ad = stb + ATILE + swz(wn + bt * 16 + r, kb + cg * 16);
                LDSM_X4(bf[bt][0], bf[bt][1], bf[bt][2], bf[bt][3], ad);
            }
            #pragma unroll
            for (int nt = 0; nt < NTT; nt++) {
                uint32_t b0 = bf[nt >> 1][nt & 1], b1 = bf[nt >> 1][2 + (nt & 1)];
                #pragma unroll
                for (int mt = 0; mt < MT; mt++) MMA_F32ACC(accf[mt][nt], av[mt], b0, b1);
            }
            // lo product: fp16 accum (reuse B frags)
            #pragma unroll
            for (int bt = 0; bt < BT; bt++) {
                uint32_t ad = stb + ATILE + WTILE + swz(wn + bt * 16 + r, kb + cg * 16);
                LDSM_X4(bf[bt][0], bf[bt][1], bf[bt][2], bf[bt][3], ad);
            }
            #pragma unroll
            for (int nt = 0; nt < NTT; nt++) {
                uint32_t b0 = bf[nt >> 1][nt & 1], b1 = bf[nt >> 1][2 + (nt & 1)];
                #pragma unroll
                for (int mt = 0; mt < MT; mt++) MMA_F16ACC(acch[mt][nt], av[mt], b0, b1);
            }
        }
    }

    // ---- epilogue: out = accf + f32(acch)/2048 (+bias) ----
    const int g = lane >> 2, tg = lane & 3;
    #pragma unroll
    for (int mt = 0; mt < MT; mt++)
        #pragma unroll
        for (int nt = 0; nt < NTT; nt++) {
            int row = m0 + wm + mt * 16 + g;
            int col = n0 + wn + nt * 8 + tg * 2;
            float b0v = 0.f, b1v = 0.f;
            if (bias) { b0v = __ldg(&bias[col]); b1v = __ldg(&bias[col + 1]); }
            __half2 l01 = *(__half2*)&acch[mt][nt][0];   // row g,   cols col, col+1
            __half2 l23 = *(__half2*)&acch[mt][nt][1];   // row g+8
            float2* d0 = (float2*)&C[(size_t)row * N + col];
            float2* d1 = (float2*)&C[(size_t)(row + 8) * N + col];
            *d0 = make_float2(accf[mt][nt][0] + __half2float(l01.x) * LO_INV + b0v,
                              accf[mt][nt][1] + __half2float(l01.y) * LO_INV + b1v);
            *d1 = make_float2(accf[mt][nt][2] + __half2float(l23.x) * LO_INV + b0v,
                              accf[mt][nt][3] + __half2float(l23.y) * LO_INV + b1v);
        }
}

// ---------------- local-window attention, smem-tiled; fp16 output ----------------
#define QBLK 64
#define JMAX (QBLK + 2*WIN)   // 78

__global__ void __launch_bounds__(256)
local_attn(const float* __restrict__ qkv, __half* __restrict__ oatt)
{
    __shared__ float ks[JMAX][DH];
    __shared__ float vs[JMAX][DH];

    const int blk = blockIdx.x;
    const int nblk = NSEQ / QBLK;          // 32
    const int i0 = (blk % nblk) * QBLK;
    const int h  = (blk / nblk) % NH;
    const int b  = blk / (nblk * NH);

    const int tid = threadIdx.x, wid = tid >> 5, lane = tid & 31;
    const int doff = h * DH;
    const size_t rbase = (size_t)b * NSEQ;

    const int jbase = (i0 - WIN > 0) ? i0 - WIN : 0;
    const int jend  = (i0 + QBLK - 1 + WIN < NSEQ - 1) ? i0 + QBLK - 1 + WIN : NSEQ - 1;
    const int jtot  = jend - jbase + 1;

    for (int s = tid; s < jtot * 32; s += 256) {
        const int row = s >> 5, c2 = (s & 31) * 2;
        const size_t g = (rbase + jbase + row) * C3 + doff + c2;
        *(float2*)&ks[row][c2] = *(const float2*)(qkv + g + CH);
        *(float2*)&vs[row][c2] = *(const float2*)(qkv + g + 2 * CH);
    }
    __syncthreads();

    const float scale = 0.125f;
    #pragma unroll
    for (int qq = 0; qq < 8; qq++) {
        const int i = i0 + wid * 8 + qq;
        const float2 q = *(const float2*)(qkv + (rbase + i) * C3 + doff + 2 * lane);
        const int j0 = (i - WIN > 0) ? i - WIN : 0;
        const int j1 = (i + WIN < NSEQ - 1) ? i + WIN : NSEQ - 1;
        const int nj = j1 - j0 + 1;
        const int rb = j0 - jbase;

        float lg[2 * WIN + 1];
        for (int jj = 0; jj < nj; jj++) {
            const float2 k = *(const float2*)&ks[rb + jj][2 * lane];
            float s = q.x * k.x + q.y * k.y;
            #pragma unroll
            for (int o = 16; o; o >>= 1) s += __shfl_xor_sync(0xffffffffu, s, o);
            lg[jj] = s * scale;
        }
        float m = -1e30f;
        for (int jj = 0; jj < nj; jj++) m = fmaxf(m, lg[jj]);
        float den = 0.f;
        float2 acc = make_float2(0.f, 0.f);
        for (int jj = 0; jj < nj; jj++) {
            const float p = __expf(lg[jj] - m);
            den += p;
            const float2 v = *(const float2*)&vs[rb + jj][2 * lane];
            acc.x += p * v.x; acc.y += p * v.y;
        }
        const float inv = 1.f / den;
        const size_t off = (rbase + i) * CH + doff + 2 * lane;
        *(__half2*)(oatt + off) = __floats2half2_rn(acc.x * inv, acc.y * inv);
    }
}

// ---------------- launch ----------------
extern "C" void kernel_launch(void* const* d_in, const int* in_sizes, int n_in,
                              void* d_out, int out_size)
{
    const float* x      = (const float*)d_in[0];
    const float* w_qkv  = (const float*)d_in[1];
    const float* w_proj = (const float*)d_in[2];
    const float* b_proj = (const float*)d_in[3];
    float* out = (float*)d_out;

    float* qkv;
    __half *x16, *qhi, *qlo, *phi, *plo, *att;
    cudaGetSymbolAddress((void**)&qkv, g_qkv);
    cudaGetSymbolAddress((void**)&x16, g_x16);
    cudaGetSymbolAddress((void**)&qhi, g_qhi); cudaGetSymbolAddress((void**)&qlo, g_qlo);
    cudaGetSymbolAddress((void**)&phi, g_phi); cudaGetSymbolAddress((void**)&plo, g_plo);
    cudaGetSymbolAddress((void**)&att, g_att);

    // QKV: BM=64, BN=128 -> stage 40KB, 2 stages = 80KB/CTA, 2 CTAs/SM
    constexpr int SMEM_QKV  = 2 * (64 * 128 + 2 * 128 * 128);    // 81920
    // Proj: BM=64, BN=192 -> stage 56KB, 2 stages = 112KB/CTA, 2 CTAs/SM
    constexpr int SMEM_PROJ = 2 * (64 * 128 + 2 * 192 * 128);    // 114688
    cudaFuncSetAttribute((void*)gemm2<64, 128>, cudaFuncAttributeMaxDynamicSharedMemorySize, SMEM_QKV);
    cudaFuncSetAttribute((void*)gemm2<64, 192>, cudaFuncAttributeMaxDynamicSharedMemorySize, SMEM_PROJ);

    // 1) fused conversions
    {
        const int n4 = N4_X + N4_Q + N4_P;
        split_all<<<(n4 + 255) / 256, 256>>>(x, w_qkv, w_proj,
                                             x16, qhi, qlo, phi, plo);
    }
    // 2) QKV GEMM: [4096, 2304] — 1152 CTAs = 1.95 waves at 2/SM
    {
        dim3 grid(C3 / 128, MTOT / 64);    // 18 x 64
        gemm2<64, 128><<<grid, 256, SMEM_QKV>>>(x16, qhi, qlo, nullptr, qkv, C3);
    }
    // 3) attention -> fp16
    {
        const int blocks = BATCH * NH * (NSEQ / QBLK);  // 768
        local_attn<<<blocks, 256>>>(qkv, att);
    }
    // 4) proj GEMM: [4096, 768] + bias — 256 CTAs = one wave
    {
        dim3 grid(CH / 192, MTOT / 64);    // 4 x 64
        gemm2<64, 192><<<grid, 256, SMEM_PROJ>>>(att, phi, plo, b_proj, out, CH);
    }
}

// round 10
// speedup vs baseline: 1.3915x; 1.3915x over previous
#include <cuda_runtime.h>
#include <cuda_fp16.h>
#include <cstdint>

#define BATCH 2
#define NSEQ  2048
#define CH    768
#define NH    12
#define DH    64
#define WIN   7
#define C3    (3*CH)
#define MTOT  (BATCH*NSEQ)   // 4096
#define KDIM  CH             // 768
#define BK    64
#define NCHUNK (KDIM/BK)     // 12

// ---------------- scratch (allocation-free) ----------------
__device__ float g_qkv[(size_t)MTOT*C3];
__device__ __half g_x16[(size_t)MTOT*CH];
__device__ __half g_wq16[(size_t)C3*CH];
__device__ __half g_wp16[(size_t)CH*CH];
__device__ __half g_att[(size_t)MTOT*CH];

// ---------------- helpers ----------------
__device__ __forceinline__ uint32_t smem_u32(const void* p) {
    uint32_t a;
    asm("{ .reg .u64 t; cvta.to.shared.u64 t, %1; cvt.u32.u64 %0, t; }" : "=r"(a) : "l"(p));
    return a;
}
__device__ __forceinline__ void cp16(uint32_t dst, const void* src) {
    asm volatile("cp.async.cg.shared.global [%0], [%1], 16;" :: "r"(dst), "l"(src) : "memory");
}
#define CP_COMMIT() asm volatile("cp.async.commit_group;" ::: "memory")
#define CP_WAIT0()  asm volatile("cp.async.wait_group 0;" ::: "memory")

#define LDSM_X4(r0, r1, r2, r3, addr)                                            \
    asm volatile("ldmatrix.sync.aligned.m8n8.x4.shared.b16 {%0,%1,%2,%3}, [%4];" \
                 : "=r"(r0), "=r"(r1), "=r"(r2), "=r"(r3) : "r"(addr))

#define MMA_F16(acc, a, b0, b1)                                               \
    asm("mma.sync.aligned.m16n8k16.row.col.f32.f16.f16.f32 "                  \
        "{%0,%1,%2,%3},{%4,%5,%6,%7},{%8,%9},{%0,%1,%2,%3};"                  \
        : "+f"((acc)[0]), "+f"((acc)[1]), "+f"((acc)[2]), "+f"((acc)[3])      \
        : "r"((a)[0]), "r"((a)[1]), "r"((a)[2]), "r"((a)[3]),                 \
          "r"(b0), "r"(b1))

// swizzled offset within rows x 128B tile: full 8-position 16B permutation
__device__ __forceinline__ uint32_t swz(int row, int colb) {
    return (uint32_t)(row * 128 + (colb ^ ((row & 7) << 4)));
}

// ---------------- fused fp32 -> fp16 conversions ----------------
#define N4_X  (MTOT*CH/4)
#define N4_Q  (C3*CH/4)
#define N4_P  (CH*CH/4)

__device__ __forceinline__ void conv4(const float* __restrict__ in,
                                      __half* __restrict__ o, int idx)
{
    float4 v = ((const float4*)in)[idx];
    __half2* op = (__half2*)(o + 4 * (size_t)idx);
    op[0] = __floats2half2_rn(v.x, v.y);
    op[1] = __floats2half2_rn(v.z, v.w);
}

__global__ void __launch_bounds__(256)
conv_all(const float* __restrict__ x, const float* __restrict__ wq,
         const float* __restrict__ wp,
         __half* __restrict__ x16, __half* __restrict__ wq16,
         __half* __restrict__ wp16)
{
    int idx = blockIdx.x * blockDim.x + threadIdx.x;
    if (idx < N4_X)                    conv4(x, x16, idx);
    else if (idx < N4_X + N4_Q)        conv4(wq, wq16, idx - N4_X);
    else if (idx < N4_X + N4_Q + N4_P) conv4(wp, wp16, idx - N4_X - N4_Q);
}

// ---------------- HMMA GEMM: single fp16 product, fp32 accum ----------------
// Stage layout: [A BM*128][W BN*128]
template<int BM_, int BN_>
__global__ void __launch_bounds__(256, 2)
gemm1(const __half* __restrict__ A, const __half* __restrict__ W,
      const float* __restrict__ bias, float* __restrict__ C, int N)
{
    constexpr int MT     = BM_ / 32;       // m16 tiles per warp (2 warp rows)
    constexpr int NTT    = BN_ / 32;       // n8 tiles per warp (4 warp cols)
    constexpr int BT     = NTT / 2;        // 16-row B LDSM groups per warp
    constexpr int ATILE  = BM_ * 128;
    constexpr int WTILE  = BN_ * 128;
    constexpr int STAGEB = ATILE + WTILE;

    extern __shared__ char smem[];
    const uint32_t sb = smem_u32(smem);
    const int tid = threadIdx.x, wid = tid >> 5, lane = tid & 31;
    const int m0 = blockIdx.y * BM_, n0 = blockIdx.x * BN_;
    const int wm = (wid >> 2) * (BM_ / 2);
    const int wn = (wid & 3) * (BN_ / 4);

    const char* pA = (const char*)A;
    const char* pW = (const char*)W;

    float acc[MT][NTT][4];
    #pragma unroll
    for (int i = 0; i < MT; i++)
        #pragma unroll
        for (int j = 0; j < NTT; j++)
            #pragma unroll
            for (int t = 0; t < 4; t++) acc[i][j][t] = 0.f;

    auto fill_stage = [&](uint32_t stb, int k0) {
        #pragma unroll
        for (int s = tid; s < BM_ * 8; s += 256) {
            int row = s >> 3, ks = s & 7;
            uint32_t so = swz(row, ks * 16);
            size_t ga = ((size_t)(m0 + row) * KDIM + k0 + ks * 8) * 2;
            cp16(stb + so, pA + ga);
        }
        #pragma unroll
        for (int s = tid; s < BN_ * 8; s += 256) {
            int row = s >> 3, ks = s & 7;
            uint32_t so = swz(row, ks * 16);
            size_t gw = ((size_t)(n0 + row) * KDIM + k0 + ks * 8) * 2;
            cp16(stb + ATILE + so, pW + gw);
        }
    };

    // prologue
    fill_stage(sb, 0);
    CP_COMMIT();

    const int r = lane & 15, cg = lane >> 4;

    #pragma unroll 1
    for (int c = 0; c < NCHUNK; c++) {
        const uint32_t stb = sb + (c & 1) * STAGEB;

        CP_WAIT0();
        __syncthreads();

        if (c + 1 < NCHUNK)
            fill_stage(sb + ((c + 1) & 1) * STAGEB, (c + 1) * BK);
        CP_COMMIT();

        #pragma unroll
        for (int kstep = 0; kstep < 4; kstep++) {
            const int kb = kstep * 32;
            uint32_t av[MT][4], bf[BT][4];
            #pragma unroll
            for (int mt = 0; mt < MT; mt++) {
                uint32_t ad = stb + swz(wm + mt * 16 + r, kb + cg * 16);
                LDSM_X4(av[mt][0], av[mt][1], av[mt][2], av[mt][3], ad);
            }
            #pragma unroll
            for (int bt = 0; bt < BT; bt++) {
                uint32_t ad = stb + ATILE + swz(wn + bt * 16 + r, kb + cg * 16);
                LDSM_X4(bf[bt][0], bf[bt][1], bf[bt][2], bf[bt][3], ad);
            }
            #pragma unroll
            for (int nt = 0; nt < NTT; nt++) {
                uint32_t b0 = bf[nt >> 1][nt & 1], b1 = bf[nt >> 1][2 + (nt & 1)];
                #pragma unroll
                for (int mt = 0; mt < MT; mt++) MMA_F16(acc[mt][nt], av[mt], b0, b1);
            }
        }
    }

    // ---- epilogue ----
    const int g = lane >> 2, tg = lane & 3;
    #pragma unroll
    for (int mt = 0; mt < MT; mt++)
        #pragma unroll
        for (int nt = 0; nt < NTT; nt++) {
            int row = m0 + wm + mt * 16 + g;
            int col = n0 + wn + nt * 8 + tg * 2;
            float b0v = 0.f, b1v = 0.f;
            if (bias) { b0v = __ldg(&bias[col]); b1v = __ldg(&bias[col + 1]); }
            float2* d0 = (float2*)&C[(size_t)row * N + col];
            float2* d1 = (float2*)&C[(size_t)(row + 8) * N + col];
            *d0 = make_float2(acc[mt][nt][0] + b0v, acc[mt][nt][1] + b1v);
            *d1 = make_float2(acc[mt][nt][2] + b0v, acc[mt][nt][3] + b1v);
        }
}

// ---------------- local-window attention, smem-tiled; fp16 output ----------------
#define QBLK 64
#define JMAX (QBLK + 2*WIN)   // 78

__global__ void __launch_bounds__(256)
local_attn(const float* __restrict__ qkv, __half* __restrict__ oatt)
{
    __shared__ float ks[JMAX][DH];
    __shared__ float vs[JMAX][DH];

    const int blk = blockIdx.x;
    const int nblk = NSEQ / QBLK;          // 32
    const int i0 = (blk % nblk) * QBLK;
    const int h  = (blk / nblk) % NH;
    const int b  = blk / (nblk * NH);

    const int tid = threadIdx.x, wid = tid >> 5, lane = tid & 31;
    const int doff = h * DH;
    const size_t rbase = (size_t)b * NSEQ;

    const int jbase = (i0 - WIN > 0) ? i0 - WIN : 0;
    const int jend  = (i0 + QBLK - 1 + WIN < NSEQ - 1) ? i0 + QBLK - 1 + WIN : NSEQ - 1;
    const int jtot  = jend - jbase + 1;

    for (int s = tid; s < jtot * 32; s += 256) {
        const int row = s >> 5, c2 = (s & 31) * 2;
        const size_t g = (rbase + jbase + row) * C3 + doff + c2;
        *(float2*)&ks[row][c2] = *(const float2*)(qkv + g + CH);
        *(float2*)&vs[row][c2] = *(const float2*)(qkv + g + 2 * CH);
    }
    __syncthreads();

    const float scale = 0.125f;
    #pragma unroll
    for (int qq = 0; qq < 8; qq++) {
        const int i = i0 + wid * 8 + qq;
        const float2 q = *(const float2*)(qkv + (rbase + i) * C3 + doff + 2 * lane);
        const int j0 = (i - WIN > 0) ? i - WIN : 0;
        const int j1 = (i + WIN < NSEQ - 1) ? i + WIN : NSEQ - 1;
        const int nj = j1 - j0 + 1;
        const int rb = j0 - jbase;

        float lg[2 * WIN + 1];
        for (int jj = 0; jj < nj; jj++) {
            const float2 k = *(const float2*)&ks[rb + jj][2 * lane];
            float s = q.x * k.x + q.y * k.y;
            #pragma unroll
            for (int o = 16; o; o >>= 1) s += __shfl_xor_sync(0xffffffffu, s, o);
            lg[jj] = s * scale;
        }
        float m = -1e30f;
        for (int jj = 0; jj < nj; jj++) m = fmaxf(m, lg[jj]);
        float den = 0.f;
        float2 acc = make_float2(0.f, 0.f);
        for (int jj = 0; jj < nj; jj++) {
            const float p = __expf(lg[jj] - m);
            den += p;
            const float2 v = *(const float2*)&vs[rb + jj][2 * lane];
            acc.x += p * v.x; acc.y += p * v.y;
        }
        const float inv = 1.f / den;
        const size_t off = (rbase + i) * CH + doff + 2 * lane;
        *(__half2*)(oatt + off) = __floats2half2_rn(acc.x * inv, acc.y * inv);
    }
}

// ---------------- launch ----------------
extern "C" void kernel_launch(void* const* d_in, const int* in_sizes, int n_in,
                              void* d_out, int out_size)
{
    const float* x      = (const float*)d_in[0];
    const float* w_qkv  = (const float*)d_in[1];
    const float* w_proj = (const float*)d_in[2];
    const float* b_proj = (const float*)d_in[3];
    float* out = (float*)d_out;

    float* qkv;
    __half *x16, *wq16, *wp16, *att;
    cudaGetSymbolAddress((void**)&qkv, g_qkv);
    cudaGetSymbolAddress((void**)&x16, g_x16);
    cudaGetSymbolAddress((void**)&wq16, g_wq16);
    cudaGetSymbolAddress((void**)&wp16, g_wp16);
    cudaGetSymbolAddress((void**)&att, g_att);

    // QKV: BM=128, BN=128 -> stage 32KB, 2 stages = 64KB/CTA, 2 CTAs/SM
    constexpr int SMEM_QKV  = 2 * (128 * 128 + 128 * 128);   // 65536
    // Proj: BM=64, BN=192 -> stage 32KB, 2 stages = 64KB/CTA, 2 CTAs/SM
    constexpr int SMEM_PROJ = 2 * (64 * 128 + 192 * 128);    // 65536
    cudaFuncSetAttribute((void*)gemm1<128, 128>, cudaFuncAttributeMaxDynamicSharedMemorySize, SMEM_QKV);
    cudaFuncSetAttribute((void*)gemm1<64, 192>,  cudaFuncAttributeMaxDynamicSharedMemorySize, SMEM_PROJ);

    // 1) fused conversions
    {
        const int n4 = N4_X + N4_Q + N4_P;
        conv_all<<<(n4 + 255) / 256, 256>>>(x, w_qkv, w_proj, x16, wq16, wp16);
    }
    // 2) QKV GEMM: [4096, 2304] — 576 CTAs = 1.95 waves at 2/SM
    {
        dim3 grid(C3 / 128, MTOT / 128);   // 18 x 32
        gemm1<128, 128><<<grid, 256, SMEM_QKV>>>(x16, wq16, nullptr, qkv, C3);
    }
    // 3) attention -> fp16
    {
        const int blocks = BATCH * NH * (NSEQ / QBLK);  // 768
        local_attn<<<blocks, 256>>>(qkv, att);
    }
    // 4) proj GEMM: [4096, 768] + bias — 256 CTAs = one wave
    {
        dim3 grid(CH / 192, MTOT / 64);    // 4 x 64
        gemm1<64, 192><<<grid, 256, SMEM_PROJ>>>(att, wp16, b_proj, out, CH);
    }
}

// round 11
// speedup vs baseline: 1.6792x; 1.2068x over previous
#include <cuda_runtime.h>
#include <cuda_fp16.h>
#include <cstdint>

#define BATCH 2
#define NSEQ  2048
#define CH    768
#define NH    12
#define DH    64
#define WIN   7
#define C3    (3*CH)
#define MTOT  (BATCH*NSEQ)   // 4096
#define KDIM  CH             // 768
#define BK    64
#define NCHUNK (KDIM/BK)     // 12

// ---------------- scratch (allocation-free) ----------------
__device__ float g_qkv[(size_t)MTOT*C3];
__device__ __half g_x16[(size_t)MTOT*CH];
__device__ __half g_wq16[(size_t)C3*CH];
__device__ __half g_wp16[(size_t)CH*CH];
__device__ __half g_att[(size_t)MTOT*CH];

// ---------------- helpers ----------------
__device__ __forceinline__ uint32_t smem_u32(const void* p) {
    uint32_t a;
    asm("{ .reg .u64 t; cvta.to.shared.u64 t, %1; cvt.u32.u64 %0, t; }" : "=r"(a) : "l"(p));
    return a;
}
__device__ __forceinline__ void cp16(uint32_t dst, const void* src) {
    asm volatile("cp.async.cg.shared.global [%0], [%1], 16;" :: "r"(dst), "l"(src) : "memory");
}
#define CP_COMMIT() asm volatile("cp.async.commit_group;" ::: "memory")
#define CP_WAIT0()  asm volatile("cp.async.wait_group 0;" ::: "memory")

#define LDSM_X4(r0, r1, r2, r3, addr)                                            \
    asm volatile("ldmatrix.sync.aligned.m8n8.x4.shared.b16 {%0,%1,%2,%3}, [%4];" \
                 : "=r"(r0), "=r"(r1), "=r"(r2), "=r"(r3) : "r"(addr))

#define MMA_F16(acc, a, b0, b1)                                               \
    asm("mma.sync.aligned.m16n8k16.row.col.f32.f16.f16.f32 "                  \
        "{%0,%1,%2,%3},{%4,%5,%6,%7},{%8,%9},{%0,%1,%2,%3};"                  \
        : "+f"((acc)[0]), "+f"((acc)[1]), "+f"((acc)[2]), "+f"((acc)[3])      \
        : "r"((a)[0]), "r"((a)[1]), "r"((a)[2]), "r"((a)[3]),                 \
          "r"(b0), "r"(b1))

__device__ __forceinline__ uint32_t swz(int row, int colb) {
    return (uint32_t)(row * 128 + (colb ^ ((row & 7) << 4)));
}

// ---------------- fused fp32 -> fp16 conversions ----------------
#define N4_X  (MTOT*CH/4)
#define N4_Q  (C3*CH/4)
#define N4_P  (CH*CH/4)

__device__ __forceinline__ void conv4(const float* __restrict__ in,
                                      __half* __restrict__ o, int idx)
{
    float4 v = ((const float4*)in)[idx];
    __half2* op = (__half2*)(o + 4 * (size_t)idx);
    op[0] = __floats2half2_rn(v.x, v.y);
    op[1] = __floats2half2_rn(v.z, v.w);
}

__global__ void __launch_bounds__(256)
conv_all(const float* __restrict__ x, const float* __restrict__ wq,
         const float* __restrict__ wp,
         __half* __restrict__ x16, __half* __restrict__ wq16,
         __half* __restrict__ wp16)
{
    int idx = blockIdx.x * blockDim.x + threadIdx.x;
    if (idx < N4_X)                    conv4(x, x16, idx);
    else if (idx < N4_X + N4_Q)        conv4(wq, wq16, idx - N4_X);
    else if (idx < N4_X + N4_Q + N4_P) conv4(wp, wp16, idx - N4_X - N4_Q);
}

// ---------------- HMMA GEMM: single fp16 product, fp32 accum ----------------
// Stage layout: [A BM*128][W BN*128]
template<int BM_, int BN_>
__global__ void __launch_bounds__(256, 2)
gemm1(const __half* __restrict__ A, const __half* __restrict__ W,
      const float* __restrict__ bias, float* __restrict__ C, int N)
{
    constexpr int MT     = BM_ / 32;
    constexpr int NTT    = BN_ / 32;
    constexpr int BT     = NTT / 2;
    constexpr int ATILE  = BM_ * 128;
    constexpr int WTILE  = BN_ * 128;
    constexpr int STAGEB = ATILE + WTILE;

    extern __shared__ char smem[];
    const uint32_t sb = smem_u32(smem);
    const int tid = threadIdx.x, wid = tid >> 5, lane = tid & 31;
    const int m0 = blockIdx.y * BM_, n0 = blockIdx.x * BN_;
    const int wm = (wid >> 2) * (BM_ / 2);
    const int wn = (wid & 3) * (BN_ / 4);

    const char* pA = (const char*)A;
    const char* pW = (const char*)W;

    float acc[MT][NTT][4];
    #pragma unroll
    for (int i = 0; i < MT; i++)
        #pragma unroll
        for (int j = 0; j < NTT; j++)
            #pragma unroll
            for (int t = 0; t < 4; t++) acc[i][j][t] = 0.f;

    auto fill_stage = [&](uint32_t stb, int k0) {
        #pragma unroll
        for (int s = tid; s < BM_ * 8; s += 256) {
            int row = s >> 3, ks = s & 7;
            uint32_t so = swz(row, ks * 16);
            size_t ga = ((size_t)(m0 + row) * KDIM + k0 + ks * 8) * 2;
            cp16(stb + so, pA + ga);
        }
        #pragma unroll
        for (int s = tid; s < BN_ * 8; s += 256) {
            int row = s >> 3, ks = s & 7;
            uint32_t so = swz(row, ks * 16);
            size_t gw = ((size_t)(n0 + row) * KDIM + k0 + ks * 8) * 2;
            cp16(stb + ATILE + so, pW + gw);
        }
    };

    fill_stage(sb, 0);
    CP_COMMIT();

    const int r = lane & 15, cg = lane >> 4;

    #pragma unroll 1
    for (int c = 0; c < NCHUNK; c++) {
        const uint32_t stb = sb + (c & 1) * STAGEB;

        CP_WAIT0();
        __syncthreads();

        if (c + 1 < NCHUNK)
            fill_stage(sb + ((c + 1) & 1) * STAGEB, (c + 1) * BK);
        CP_COMMIT();

        #pragma unroll
        for (int kstep = 0; kstep < 4; kstep++) {
            const int kb = kstep * 32;
            uint32_t av[MT][4], bf[BT][4];
            #pragma unroll
            for (int mt = 0; mt < MT; mt++) {
                uint32_t ad = stb + swz(wm + mt * 16 + r, kb + cg * 16);
                LDSM_X4(av[mt][0], av[mt][1], av[mt][2], av[mt][3], ad);
            }
            #pragma unroll
            for (int bt = 0; bt < BT; bt++) {
                uint32_t ad = stb + ATILE + swz(wn + bt * 16 + r, kb + cg * 16);
                LDSM_X4(bf[bt][0], bf[bt][1], bf[bt][2], bf[bt][3], ad);
            }
            #pragma unroll
            for (int nt = 0; nt < NTT; nt++) {
                uint32_t b0 = bf[nt >> 1][nt & 1], b1 = bf[nt >> 1][2 + (nt & 1)];
                #pragma unroll
                for (int mt = 0; mt < MT; mt++) MMA_F16(acc[mt][nt], av[mt], b0, b1);
            }
        }
    }

    const int g = lane >> 2, tg = lane & 3;
    #pragma unroll
    for (int mt = 0; mt < MT; mt++)
        #pragma unroll
        for (int nt = 0; nt < NTT; nt++) {
            int row = m0 + wm + mt * 16 + g;
            int col = n0 + wn + nt * 8 + tg * 2;
            float b0v = 0.f, b1v = 0.f;
            if (bias) { b0v = __ldg(&bias[col]); b1v = __ldg(&bias[col + 1]); }
            float2* d0 = (float2*)&C[(size_t)row * N + col];
            float2* d1 = (float2*)&C[(size_t)(row + 8) * N + col];
            *d0 = make_float2(acc[mt][nt][0] + b0v, acc[mt][nt][1] + b1v);
            *d1 = make_float2(acc[mt][nt][2] + b0v, acc[mt][nt][3] + b1v);
        }
}

// ---------------- local-window attention: thread-per-query ----------------
#define QBLK  128
#define JROWS (QBLK + 2*WIN)   // 142
#define KPAD  68               // row stride (floats): 68%32=4 -> conflict-free phases
#define NWIN  (2*WIN + 1)      // 15

__global__ void __launch_bounds__(128, 2)
local_attn(const float* __restrict__ qkv, __half* __restrict__ oatt)
{
    extern __shared__ float sm[];
    float (*ks)[KPAD] = (float(*)[KPAD])sm;
    float (*vs)[KPAD] = (float(*)[KPAD])(sm + JROWS * KPAD);
    float (*qs)[KPAD] = (float(*)[KPAD])(sm + 2 * JROWS * KPAD);

    const int nblk = NSEQ / QBLK;          // 16
    const int i0 = (blockIdx.x % nblk) * QBLK;
    const int h  = (blockIdx.x / nblk) % NH;
    const int b  = blockIdx.x / (nblk * NH);

    const int tid = threadIdx.x;
    const int doff = h * DH;
    const size_t rbase = (size_t)b * NSEQ;

    const int jbase = (i0 - WIN > 0) ? i0 - WIN : 0;
    const int jend  = (i0 + QBLK - 1 + WIN < NSEQ - 1) ? i0 + QBLK - 1 + WIN : NSEQ - 1;
    const int jtot  = jend - jbase + 1;

    // stage K, V (jtot rows) and Q (QBLK rows); float2 slots, coalesced
    for (int s = tid; s < jtot * 32; s += 128) {
        const int row = s >> 5, c2 = (s & 31) * 2;
        const size_t g = (rbase + jbase + row) * C3 + doff + c2;
        *(float2*)&ks[row][c2] = *(const float2*)(qkv + g + CH);
        *(float2*)&vs[row][c2] = *(const float2*)(qkv + g + 2 * CH);
    }
    for (int s = tid; s < QBLK * 32; s += 128) {
        const int row = s >> 5, c2 = (s & 31) * 2;
        const size_t g = (rbase + i0 + row) * C3 + doff + c2;
        *(float2*)&qs[row][c2] = *(const float2*)(qkv + g);
    }
    __syncthreads();

    const int i = i0 + tid;
    const int j0 = (i - WIN > 0) ? i - WIN : 0;
    const int j1 = (i + WIN < NSEQ - 1) ? i + WIN : NSEQ - 1;
    const int nj = j1 - j0 + 1;
    const int rb = j0 - jbase;

    // ---- phase A: logits (registers only; jj fully unrolled + predicated) ----
    float lg[NWIN];
    #pragma unroll
    for (int jj = 0; jj < NWIN; jj++) lg[jj] = 0.f;

    #pragma unroll
    for (int dc = 0; dc < 4; dc++) {
        const float* qp = &qs[tid][dc * 16];
        float4 q0 = *(const float4*)(qp + 0);
        float4 q1 = *(const float4*)(qp + 4);
        float4 q2 = *(const float4*)(qp + 8);
        float4 q3 = *(const float4*)(qp + 12);
        #pragma unroll
        for (int jj = 0; jj < NWIN; jj++) {
            if (jj < nj) {
                const float* kr = &ks[rb + jj][dc * 16];
                float4 k0 = *(const float4*)(kr + 0);
                float4 k1 = *(const float4*)(kr + 4);
                float4 k2 = *(const float4*)(kr + 8);
                float4 k3 = *(const float4*)(kr + 12);
                float s = q0.x*k0.x + q0.y*k0.y + q0.z*k0.z + q0.w*k0.w
                        + q1.x*k1.x + q1.y*k1.y + q1.z*k1.z + q1.w*k1.w
                        + q2.x*k2.x + q2.y*k2.y + q2.z*k2.z + q2.w*k2.w
                        + q3.x*k3.x + q3.y*k3.y + q3.z*k3.z + q3.w*k3.w;
                lg[jj] += s;
            }
        }
    }

    // ---- softmax (scale, max, exp, normalize into lg) ----
    const float scale = 0.125f;
    float m = -1e30f;
    #pragma unroll
    for (int jj = 0; jj < NWIN; jj++) {
        if (jj < nj) { lg[jj] *= scale; m = fmaxf(m, lg[jj]); }
    }
    float den = 0.f;
    #pragma unroll
    for (int jj = 0; jj < NWIN; jj++) {
        if (jj < nj) { lg[jj] = __expf(lg[jj] - m); den += lg[jj]; }
    }
    const float inv = 1.f / den;
    #pragma unroll
    for (int jj = 0; jj < NWIN; jj++) lg[jj] *= inv;

    // ---- phase B: output = sum p_j * v_j ; write fp16 ----
    __half* orow = oatt + (rbase + i) * CH + doff;
    #pragma unroll
    for (int dc = 0; dc < 4; dc++) {
        float a0[4] = {0,0,0,0}, a1[4] = {0,0,0,0},
              a2[4] = {0,0,0,0}, a3[4] = {0,0,0,0};
        #pragma unroll
        for (int jj = 0; jj < NWIN; jj++) {
            if (jj < nj) {
                const float p = lg[jj];
                const float* vr = &vs[rb + jj][dc * 16];
                float4 v0 = *(const float4*)(vr + 0);
                float4 v1 = *(const float4*)(vr + 4);
                float4 v2 = *(const float4*)(vr + 8);
                float4 v3 = *(const float4*)(vr + 12);
                a0[0] += p*v0.x; a0[1] += p*v0.y; a0[2] += p*v0.z; a0[3] += p*v0.w;
                a1[0] += p*v1.x; a1[1] += p*v1.y; a1[2] += p*v1.z; a1[3] += p*v1.w;
                a2[0] += p*v2.x; a2[1] += p*v2.y; a2[2] += p*v2.z; a2[3] += p*v2.w;
                a3[0] += p*v3.x; a3[1] += p*v3.y; a3[2] += p*v3.z; a3[3] += p*v3.w;
            }
        }
        __half2 hb[8];
        hb[0] = __floats2half2_rn(a0[0], a0[1]); hb[1] = __floats2half2_rn(a0[2], a0[3]);
        hb[2] = __floats2half2_rn(a1[0], a1[1]); hb[3] = __floats2half2_rn(a1[2], a1[3]);
        hb[4] = __floats2half2_rn(a2[0], a2[1]); hb[5] = __floats2half2_rn(a2[2], a2[3]);
        hb[6] = __floats2half2_rn(a3[0], a3[1]); hb[7] = __floats2half2_rn(a3[2], a3[3]);
        uint4* dst = (uint4*)(orow + dc * 16);
        dst[0] = *(uint4*)&hb[0];
        dst[1] = *(uint4*)&hb[4];
    }
}

// ---------------- launch ----------------
extern "C" void kernel_launch(void* const* d_in, const int* in_sizes, int n_in,
                              void* d_out, int out_size)
{
    const float* x      = (const float*)d_in[0];
    const float* w_qkv  = (const float*)d_in[1];
    const float* w_proj = (const float*)d_in[2];
    const float* b_proj = (const float*)d_in[3];
    float* out = (float*)d_out;

    float* qkv;
    __half *x16, *wq16, *wp16, *att;
    cudaGetSymbolAddress((void**)&qkv, g_qkv);
    cudaGetSymbolAddress((void**)&x16, g_x16);
    cudaGetSymbolAddress((void**)&wq16, g_wq16);
    cudaGetSymbolAddress((void**)&wp16, g_wp16);
    cudaGetSymbolAddress((void**)&att, g_att);

    constexpr int SMEM_QKV  = 2 * (128 * 128 + 128 * 128);   // 65536
    constexpr int SMEM_PROJ = 2 * (64 * 128 + 192 * 128);    // 65536
    constexpr int SMEM_ATTN = (2 * JROWS + QBLK) * KPAD * 4; // 112064
    cudaFuncSetAttribute((void*)gemm1<128, 128>, cudaFuncAttributeMaxDynamicSharedMemorySize, SMEM_QKV);
    cudaFuncSetAttribute((void*)gemm1<64, 192>,  cudaFuncAttributeMaxDynamicSharedMemorySize, SMEM_PROJ);
    cudaFuncSetAttribute((void*)local_attn,      cudaFuncAttributeMaxDynamicSharedMemorySize, SMEM_ATTN);

    // 1) fused conversions
    {
        const int n4 = N4_X + N4_Q + N4_P;
        conv_all<<<(n4 + 255) / 256, 256>>>(x, w_qkv, w_proj, x16, wq16, wp16);
    }
    // 2) QKV GEMM: [4096, 2304] — 576 CTAs = 1.95 waves at 2/SM
    {
        dim3 grid(C3 / 128, MTOT / 128);   // 18 x 32
        gemm1<128, 128><<<grid, 256, SMEM_QKV>>>(x16, wq16, nullptr, qkv, C3);
    }
    // 3) attention -> fp16 (thread-per-query)
    {
        const int blocks = BATCH * NH * (NSEQ / QBLK);  // 384
        local_attn<<<blocks, 128, SMEM_ATTN>>>(qkv, att);
    }
    // 4) proj GEMM: [4096, 768] + bias — 256 CTAs = one wave
    {
        dim3 grid(CH / 192, MTOT / 64);    // 4 x 64
        gemm1<64, 192><<<grid, 256, SMEM_PROJ>>>(att, wp16, b_proj, out, CH);
    }
}

// round 12
// speedup vs baseline: 1.8620x; 1.1089x over previous
#include <cuda_runtime.h>
#include <cuda_fp16.h>
#include <cstdint>

#define BATCH 2
#define NSEQ  2048
#define CH    768
#define NH    12
#define DH    64
#define WIN   7
#define C3    (3*CH)
#define MTOT  (BATCH*NSEQ)   // 4096
#define KDIM  CH             // 768
#define BK    64
#define NCHUNK (KDIM/BK)     // 12

// ---------------- scratch (allocation-free) ----------------
__device__ float g_qkv[(size_t)MTOT*C3];
__device__ __half g_x16[(size_t)MTOT*CH];
__device__ __half g_wq16[(size_t)C3*CH];
__device__ __half g_wp16[(size_t)CH*CH];
__device__ __half g_att[(size_t)MTOT*CH];

// ---------------- helpers ----------------
__device__ __forceinline__ uint32_t smem_u32(const void* p) {
    uint32_t a;
    asm("{ .reg .u64 t; cvta.to.shared.u64 t, %1; cvt.u32.u64 %0, t; }" : "=r"(a) : "l"(p));
    return a;
}
__device__ __forceinline__ void cp16(uint32_t dst, const void* src) {
    asm volatile("cp.async.cg.shared.global [%0], [%1], 16;" :: "r"(dst), "l"(src) : "memory");
}
#define CP_COMMIT() asm volatile("cp.async.commit_group;" ::: "memory")
#define CP_WAIT1()  asm volatile("cp.async.wait_group 1;" ::: "memory")

#define LDSM_X4(r0, r1, r2, r3, addr)                                            \
    asm volatile("ldmatrix.sync.aligned.m8n8.x4.shared.b16 {%0,%1,%2,%3}, [%4];" \
                 : "=r"(r0), "=r"(r1), "=r"(r2), "=r"(r3) : "r"(addr))

#define MMA_F16(acc, a, b0, b1)                                               \
    asm("mma.sync.aligned.m16n8k16.row.col.f32.f16.f16.f32 "                  \
        "{%0,%1,%2,%3},{%4,%5,%6,%7},{%8,%9},{%0,%1,%2,%3};"                  \
        : "+f"((acc)[0]), "+f"((acc)[1]), "+f"((acc)[2]), "+f"((acc)[3])      \
        : "r"((a)[0]), "r"((a)[1]), "r"((a)[2]), "r"((a)[3]),                 \
          "r"(b0), "r"(b1))

__device__ __forceinline__ uint32_t swz(int row, int colb) {
    return (uint32_t)(row * 128 + (colb ^ ((row & 7) << 4)));
}

// ---------------- fused fp32 -> fp16 conversions ----------------
#define N4_X  (MTOT*CH/4)
#define N4_Q  (C3*CH/4)
#define N4_P  (CH*CH/4)

__device__ __forceinline__ void conv4(const float* __restrict__ in,
                                      __half* __restrict__ o, int idx)
{
    float4 v = ((const float4*)in)[idx];
    __half2* op = (__half2*)(o + 4 * (size_t)idx);
    op[0] = __floats2half2_rn(v.x, v.y);
    op[1] = __floats2half2_rn(v.z, v.w);
}

__global__ void __launch_bounds__(256)
conv_all(const float* __restrict__ x, const float* __restrict__ wq,
         const float* __restrict__ wp,
         __half* __restrict__ x16, __half* __restrict__ wq16,
         __half* __restrict__ wp16)
{
    int idx = blockIdx.x * blockDim.x + threadIdx.x;
    if (idx < N4_X)                    conv4(x, x16, idx);
    else if (idx < N4_X + N4_Q)        conv4(wq, wq16, idx - N4_X);
    else if (idx < N4_X + N4_Q + N4_P) conv4(wp, wp16, idx - N4_X - N4_Q);
}

// ---------------- HMMA GEMM: single fp16 product, 3-stage ring ----------------
// Stage layout: [A BM*128][W BN*128]
template<int BM_, int BN_>
__global__ void __launch_bounds__(256, 2)
gemm1(const __half* __restrict__ A, const __half* __restrict__ W,
      const float* __restrict__ bias, float* __restrict__ C, int N)
{
    constexpr int MT     = BM_ / 32;
    constexpr int NTT    = BN_ / 32;
    constexpr int BT     = NTT / 2;
    constexpr int ATILE  = BM_ * 128;
    constexpr int WTILE  = BN_ * 128;
    constexpr int STAGEB = ATILE + WTILE;

    extern __shared__ char smem[];
    const uint32_t sb = smem_u32(smem);
    const int tid = threadIdx.x, wid = tid >> 5, lane = tid & 31;
    const int m0 = blockIdx.y * BM_, n0 = blockIdx.x * BN_;
    const int wm = (wid >> 2) * (BM_ / 2);
    const int wn = (wid & 3) * (BN_ / 4);

    const char* pA = (const char*)A;
    const char* pW = (const char*)W;

    float acc[MT][NTT][4];
    #pragma unroll
    for (int i = 0; i < MT; i++)
        #pragma unroll
        for (int j = 0; j < NTT; j++)
            #pragma unroll
            for (int t = 0; t < 4; t++) acc[i][j][t] = 0.f;

    auto fill_stage = [&](uint32_t stb, int k0) {
        #pragma unroll
        for (int s = tid; s < BM_ * 8; s += 256) {
            int row = s >> 3, ks = s & 7;
            uint32_t so = swz(row, ks * 16);
            size_t ga = ((size_t)(m0 + row) * KDIM + k0 + ks * 8) * 2;
            cp16(stb + so, pA + ga);
        }
        #pragma unroll
        for (int s = tid; s < BN_ * 8; s += 256) {
            int row = s >> 3, ks = s & 7;
            uint32_t so = swz(row, ks * 16);
            size_t gw = ((size_t)(n0 + row) * KDIM + k0 + ks * 8) * 2;
            cp16(stb + ATILE + so, pW + gw);
        }
    };

    // prologue: chunks 0,1 -> stages 0,1
    fill_stage(sb, 0);           CP_COMMIT();
    fill_stage(sb + STAGEB, BK); CP_COMMIT();

    const int r = lane & 15, cg = lane >> 4;

    #pragma unroll 1
    for (int c = 0; c < NCHUNK; c++) {
        const uint32_t stb = sb + (c % 3) * STAGEB;

        CP_WAIT1();              // chunk c landed; c+1 may still be in flight
        __syncthreads();         // all warps done with stage (c+2)%3's old chunk

        if (c + 2 < NCHUNK)
            fill_stage(sb + ((c + 2) % 3) * STAGEB, (c + 2) * BK);
        CP_COMMIT();

        #pragma unroll
        for (int kstep = 0; kstep < 4; kstep++) {
            const int kb = kstep * 32;
            uint32_t av[MT][4], bf[BT][4];
            #pragma unroll
            for (int mt = 0; mt < MT; mt++) {
                uint32_t ad = stb + swz(wm + mt * 16 + r, kb + cg * 16);
                LDSM_X4(av[mt][0], av[mt][1], av[mt][2], av[mt][3], ad);
            }
            #pragma unroll
            for (int bt = 0; bt < BT; bt++) {
                uint32_t ad = stb + ATILE + swz(wn + bt * 16 + r, kb + cg * 16);
                LDSM_X4(bf[bt][0], bf[bt][1], bf[bt][2], bf[bt][3], ad);
            }
            #pragma unroll
            for (int nt = 0; nt < NTT; nt++) {
                uint32_t b0 = bf[nt >> 1][nt & 1], b1 = bf[nt >> 1][2 + (nt & 1)];
                #pragma unroll
                for (int mt = 0; mt < MT; mt++) MMA_F16(acc[mt][nt], av[mt], b0, b1);
            }
        }
    }

    const int g = lane >> 2, tg = lane & 3;
    #pragma unroll
    for (int mt = 0; mt < MT; mt++)
        #pragma unroll
        for (int nt = 0; nt < NTT; nt++) {
            int row = m0 + wm + mt * 16 + g;
            int col = n0 + wn + nt * 8 + tg * 2;
            float b0v = 0.f, b1v = 0.f;
            if (bias) { b0v = __ldg(&bias[col]); b1v = __ldg(&bias[col + 1]); }
            float2* d0 = (float2*)&C[(size_t)row * N + col];
            float2* d1 = (float2*)&C[(size_t)(row + 8) * N + col];
            *d0 = make_float2(acc[mt][nt][0] + b0v, acc[mt][nt][1] + b1v);
            *d1 = make_float2(acc[mt][nt][2] + b0v, acc[mt][nt][3] + b1v);
        }
}

// ---------------- local-window attention: thread-per-query, one wave ----------------
// K fp32 (stride 68 words), V fp16 (stride 72 halves), Q direct from gmem (L2).
#define QBLK  128
#define JROWS (QBLK + 2*WIN)   // 142
#define KPAD  68               // fp32 word stride; row*68%32=row*4 -> conflict-free
#define VPADH 72               // half stride (=36 words); same bank rotation
#define NWIN  (2*WIN + 1)      // 15
#define SMEM_ATTN (JROWS*KPAD*4 + JROWS*VPADH*2)   // 38624 + 20448 = 59072

__global__ void __launch_bounds__(128, 3)
local_attn(const float* __restrict__ qkv, __half* __restrict__ oatt)
{
    extern __shared__ float sm[];
    float (*ks)[KPAD] = (float(*)[KPAD])sm;
    __half* vsb = (__half*)(sm + JROWS * KPAD);

    const int nblk = NSEQ / QBLK;          // 16
    const int i0 = (blockIdx.x % nblk) * QBLK;
    const int h  = (blockIdx.x / nblk) % NH;
    const int b  = blockIdx.x / (nblk * NH);

    const int tid = threadIdx.x;
    const int doff = h * DH;
    const size_t rbase = (size_t)b * NSEQ;

    const int jbase = (i0 - WIN > 0) ? i0 - WIN : 0;
    const int jend  = (i0 + QBLK - 1 + WIN < NSEQ - 1) ? i0 + QBLK - 1 + WIN : NSEQ - 1;
    const int jtot  = jend - jbase + 1;

    // stage K (fp32) and V (fp16)
    for (int s = tid; s < jtot * 32; s += 128) {
        const int row = s >> 5, c2 = (s & 31) * 2;
        const size_t g = (rbase + jbase + row) * C3 + doff + c2;
        *(float2*)&ks[row][c2] = *(const float2*)(qkv + g + CH);
        float2 vv = *(const float2*)(qkv + g + 2 * CH);
        *(__half2*)(vsb + row * VPADH + c2) = __floats2half2_rn(vv.x, vv.y);
    }
    __syncthreads();

    const int i = i0 + tid;
    const int j0 = (i - WIN > 0) ? i - WIN : 0;
    const int j1 = (i + WIN < NSEQ - 1) ? i + WIN : NSEQ - 1;
    const int nj = j1 - j0 + 1;
    const int rb = j0 - jbase;

    const float* qrow = qkv + (rbase + i) * C3 + doff;

    // ---- phase A: logits ----
    float lg[NWIN];
    #pragma unroll
    for (int jj = 0; jj < NWIN; jj++) lg[jj] = 0.f;

    #pragma unroll
    for (int dc = 0; dc < 4; dc++) {
        float4 q0 = *(const float4*)(qrow + dc * 16 + 0);
        float4 q1 = *(const float4*)(qrow + dc * 16 + 4);
        float4 q2 = *(const float4*)(qrow + dc * 16 + 8);
        float4 q3 = *(const float4*)(qrow + dc * 16 + 12);
        #pragma unroll
        for (int jj = 0; jj < NWIN; jj++) {
            if (jj < nj) {
                const float* kr = &ks[rb + jj][dc * 16];
                float4 k0 = *(const float4*)(kr + 0);
                float4 k1 = *(const float4*)(kr + 4);
                float4 k2 = *(const float4*)(kr + 8);
                float4 k3 = *(const float4*)(kr + 12);
                lg[jj] += q0.x*k0.x + q0.y*k0.y + q0.z*k0.z + q0.w*k0.w
                        + q1.x*k1.x + q1.y*k1.y + q1.z*k1.z + q1.w*k1.w
                        + q2.x*k2.x + q2.y*k2.y + q2.z*k2.z + q2.w*k2.w
                        + q3.x*k3.x + q3.y*k3.y + q3.z*k3.z + q3.w*k3.w;
            }
        }
    }

    // ---- softmax ----
    const float scale = 0.125f;
    float m = -1e30f;
    #pragma unroll
    for (int jj = 0; jj < NWIN; jj++) {
        if (jj < nj) { lg[jj] *= scale; m = fmaxf(m, lg[jj]); }
    }
    float den = 0.f;
    #pragma unroll
    for (int jj = 0; jj < NWIN; jj++) {
        if (jj < nj) { lg[jj] = __expf(lg[jj] - m); den += lg[jj]; }
    }
    const float inv = 1.f / den;
    #pragma unroll
    for (int jj = 0; jj < NWIN; jj++) lg[jj] *= inv;

    // ---- phase B: output = sum p_j * v_j (V fp16 in smem) ----
    __half* orow = oatt + (rbase + i) * CH + doff;
    #pragma unroll
    for (int dc = 0; dc < 4; dc++) {
        float a[16];
        #pragma unroll
        for (int t = 0; t < 16; t++) a[t] = 0.f;
        #pragma unroll
        for (int jj = 0; jj < NWIN; jj++) {
            if (jj < nj) {
                const float p = lg[jj];
                const __half* vr = vsb + (rb + jj) * VPADH + dc * 16;
                uint4 u0 = *(const uint4*)vr;
                uint4 u1 = *(const uint4*)(vr + 8);
                const __half2* h0 = (const __half2*)&u0;
                const __half2* h1 = (const __half2*)&u1;
                #pragma unroll
                for (int t = 0; t < 4; t++) {
                    float2 f = __half22float2(h0[t]);
                    a[2*t + 0] += p * f.x;
                    a[2*t + 1] += p * f.y;
                }
                #pragma unroll
                for (int t = 0; t < 4; t++) {
                    float2 f = __half22float2(h1[t]);
                    a[8 + 2*t + 0] += p * f.x;
                    a[8 + 2*t + 1] += p * f.y;
                }
            }
        }
        __half2 hb[8];
        #pragma unroll
        for (int t = 0; t < 8; t++) hb[t] = __floats2half2_rn(a[2*t], a[2*t + 1]);
        uint4* dst = (uint4*)(orow + dc * 16);
        dst[0] = *(uint4*)&hb[0];
        dst[1] = *(uint4*)&hb[4];
    }
}

// ---------------- launch ----------------
extern "C" void kernel_launch(void* const* d_in, const int* in_sizes, int n_in,
                              void* d_out, int out_size)
{
    const float* x      = (const float*)d_in[0];
    const float* w_qkv  = (const float*)d_in[1];
    const float* w_proj = (const float*)d_in[2];
    const float* b_proj = (const float*)d_in[3];
    float* out = (float*)d_out;

    float* qkv;
    __half *x16, *wq16, *wp16, *att;
    cudaGetSymbolAddress((void**)&qkv, g_qkv);
    cudaGetSymbolAddress((void**)&x16, g_x16);
    cudaGetSymbolAddress((void**)&wq16, g_wq16);
    cudaGetSymbolAddress((void**)&wp16, g_wp16);
    cudaGetSymbolAddress((void**)&att, g_att);

    constexpr int SMEM_QKV  = 3 * (128 * 128 + 128 * 128);   // 98304
    constexpr int SMEM_PROJ = 3 * (64 * 128 + 192 * 128);    // 98304
    cudaFuncSetAttribute((void*)gemm1<128, 128>, cudaFuncAttributeMaxDynamicSharedMemorySize, SMEM_QKV);
    cudaFuncSetAttribute((void*)gemm1<64, 192>,  cudaFuncAttributeMaxDynamicSharedMemorySize, SMEM_PROJ);
    cudaFuncSetAttribute((void*)local_attn,      cudaFuncAttributeMaxDynamicSharedMemorySize, SMEM_ATTN);

    // 1) fused conversions
    {
        const int n4 = N4_X + N4_Q + N4_P;
        conv_all<<<(n4 + 255) / 256, 256>>>(x, w_qkv, w_proj, x16, wq16, wp16);
    }
    // 2) QKV GEMM: [4096, 2304]
    {
        dim3 grid(C3 / 128, MTOT / 128);   // 18 x 32
        gemm1<128, 128><<<grid, 256, SMEM_QKV>>>(x16, wq16, nullptr, qkv, C3);
    }
    // 3) attention -> fp16 (thread-per-query, one wave at 3 CTAs/SM)
    {
        const int blocks = BATCH * NH * (NSEQ / QBLK);  // 384
        local_attn<<<blocks, 128, SMEM_ATTN>>>(qkv, att);
    }
    // 4) proj GEMM: [4096, 768] + bias
    {
        dim3 grid(CH / 192, MTOT / 64);    // 4 x 64 = 256
        gemm1<64, 192><<<grid, 256, SMEM_PROJ>>>(att, wp16, b_proj, out, CH);
    }
}

// round 13
// speedup vs baseline: 1.9449x; 1.0445x over previous
#include <cuda_runtime.h>
#include <cuda_fp16.h>
#include <cstdint>

#define BATCH 2
#define NSEQ  2048
#define CH    768
#define NH    12
#define DH    64
#define WIN   7
#define C3    (3*CH)
#define C2    (2*CH)
#define MTOT  (BATCH*NSEQ)   // 4096
#define KDIM  CH             // 768
#define BK    64
#define NCHUNK (KDIM/BK)     // 12

// ---------------- scratch (allocation-free) ----------------
__device__ float  g_qk[(size_t)MTOT*C2];    // Q,K fp32 [M, 1536]
__device__ __half g_v16[(size_t)MTOT*CH];   // V fp16  [M, 768]
__device__ __half g_x16[(size_t)MTOT*CH];
__device__ __half g_wq16[(size_t)C3*CH];
__device__ __half g_wp16[(size_t)CH*CH];
__device__ __half g_att[(size_t)MTOT*CH];

// ---------------- helpers ----------------
__device__ __forceinline__ uint32_t smem_u32(const void* p) {
    uint32_t a;
    asm("{ .reg .u64 t; cvta.to.shared.u64 t, %1; cvt.u32.u64 %0, t; }" : "=r"(a) : "l"(p));
    return a;
}
__device__ __forceinline__ void cp16(uint32_t dst, const void* src) {
    asm volatile("cp.async.cg.shared.global [%0], [%1], 16;" :: "r"(dst), "l"(src) : "memory");
}
#define CP_COMMIT() asm volatile("cp.async.commit_group;" ::: "memory")
#define CP_WAIT0()  asm volatile("cp.async.wait_group 0;" ::: "memory")
#define CP_WAIT1()  asm volatile("cp.async.wait_group 1;" ::: "memory")

#define LDSM_X4(r0, r1, r2, r3, addr)                                            \
    asm volatile("ldmatrix.sync.aligned.m8n8.x4.shared.b16 {%0,%1,%2,%3}, [%4];" \
                 : "=r"(r0), "=r"(r1), "=r"(r2), "=r"(r3) : "r"(addr))

#define MMA_F16(acc, a, b0, b1)                                               \
    asm("mma.sync.aligned.m16n8k16.row.col.f32.f16.f16.f32 "                  \
        "{%0,%1,%2,%3},{%4,%5,%6,%7},{%8,%9},{%0,%1,%2,%3};"                  \
        : "+f"((acc)[0]), "+f"((acc)[1]), "+f"((acc)[2]), "+f"((acc)[3])      \
        : "r"((a)[0]), "r"((a)[1]), "r"((a)[2]), "r"((a)[3]),                 \
          "r"(b0), "r"(b1))

__device__ __forceinline__ uint32_t swz(int row, int colb) {
    return (uint32_t)(row * 128 + (colb ^ ((row & 7) << 4)));
}

// ---------------- fused fp32 -> fp16 conversions ----------------
#define N4_X  (MTOT*CH/4)
#define N4_Q  (C3*CH/4)
#define N4_P  (CH*CH/4)

__device__ __forceinline__ void conv4(const float* __restrict__ in,
                                      __half* __restrict__ o, int idx)
{
    float4 v = ((const float4*)in)[idx];
    __half2* op = (__half2*)(o + 4 * (size_t)idx);
    op[0] = __floats2half2_rn(v.x, v.y);
    op[1] = __floats2half2_rn(v.z, v.w);
}

__global__ void __launch_bounds__(256)
conv_all(const float* __restrict__ x, const float* __restrict__ wq,
         const float* __restrict__ wp,
         __half* __restrict__ x16, __half* __restrict__ wq16,
         __half* __restrict__ wp16)
{
    int idx = blockIdx.x * blockDim.x + threadIdx.x;
    if (idx < N4_X)                    conv4(x, x16, idx);
    else if (idx < N4_X + N4_Q)        conv4(wq, wq16, idx - N4_X);
    else if (idx < N4_X + N4_Q + N4_P) conv4(wp, wp16, idx - N4_X - N4_Q);
}

// ---------------- HMMA GEMM: single fp16 product, 3-stage ring ----------------
// If Cv != nullptr and this CTA's n0 >= vcol0, output goes to Cv as fp16
// at column (col - vcol0), row stride CH. Otherwise fp32 to C (stride N).
template<int BM_, int BN_>
__global__ void __launch_bounds__(256, 2)
gemm1(const __half* __restrict__ A, const __half* __restrict__ W,
      const float* __restrict__ bias, float* __restrict__ C, int N,
      __half* __restrict__ Cv, int vcol0)
{
    constexpr int MT     = BM_ / 32;
    constexpr int NTT    = BN_ / 32;
    constexpr int BT     = NTT / 2;
    constexpr int ATILE  = BM_ * 128;
    constexpr int WTILE  = BN_ * 128;
    constexpr int STAGEB = ATILE + WTILE;

    extern __shared__ char smem[];
    const uint32_t sb = smem_u32(smem);
    const int tid = threadIdx.x, wid = tid >> 5, lane = tid & 31;
    const int m0 = blockIdx.y * BM_, n0 = blockIdx.x * BN_;
    const int wm = (wid >> 2) * (BM_ / 2);
    const int wn = (wid & 3) * (BN_ / 4);

    const char* pA = (const char*)A;
    const char* pW = (const char*)W;

    float acc[MT][NTT][4];
    #pragma unroll
    for (int i = 0; i < MT; i++)
        #pragma unroll
        for (int j = 0; j < NTT; j++)
            #pragma unroll
            for (int t = 0; t < 4; t++) acc[i][j][t] = 0.f;

    auto fill_stage = [&](uint32_t stb, int k0) {
        #pragma unroll
        for (int s = tid; s < BM_ * 8; s += 256) {
            int row = s >> 3, ks = s & 7;
            uint32_t so = swz(row, ks * 16);
            size_t ga = ((size_t)(m0 + row) * KDIM + k0 + ks * 8) * 2;
            cp16(stb + so, pA + ga);
        }
        #pragma unroll
        for (int s = tid; s < BN_ * 8; s += 256) {
            int row = s >> 3, ks = s & 7;
            uint32_t so = swz(row, ks * 16);
            size_t gw = ((size_t)(n0 + row) * KDIM + k0 + ks * 8) * 2;
            cp16(stb + ATILE + so, pW + gw);
        }
    };

    // prologue: chunks 0,1 -> stages 0,1
    fill_stage(sb, 0);           CP_COMMIT();
    fill_stage(sb + STAGEB, BK); CP_COMMIT();

    const int r = lane & 15, cg = lane >> 4;

    #pragma unroll 1
    for (int c = 0; c < NCHUNK; c++) {
        const uint32_t stb = sb + (c % 3) * STAGEB;

        CP_WAIT1();
        __syncthreads();

        if (c + 2 < NCHUNK)
            fill_stage(sb + ((c + 2) % 3) * STAGEB, (c + 2) * BK);
        CP_COMMIT();

        #pragma unroll
        for (int kstep = 0; kstep < 4; kstep++) {
            const int kb = kstep * 32;
            uint32_t av[MT][4], bf[BT][4];
            #pragma unroll
            for (int mt = 0; mt < MT; mt++) {
                uint32_t ad = stb + swz(wm + mt * 16 + r, kb + cg * 16);
                LDSM_X4(av[mt][0], av[mt][1], av[mt][2], av[mt][3], ad);
            }
            #pragma unroll
            for (int bt = 0; bt < BT; bt++) {
                uint32_t ad = stb + ATILE + swz(wn + bt * 16 + r, kb + cg * 16);
                LDSM_X4(bf[bt][0], bf[bt][1], bf[bt][2], bf[bt][3], ad);
            }
            #pragma unroll
            for (int nt = 0; nt < NTT; nt++) {
                uint32_t b0 = bf[nt >> 1][nt & 1], b1 = bf[nt >> 1][2 + (nt & 1)];
                #pragma unroll
                for (int mt = 0; mt < MT; mt++) MMA_F16(acc[mt][nt], av[mt], b0, b1);
            }
        }
    }

    // ---- epilogue ----
    const int g = lane >> 2, tg = lane & 3;
    const bool vblock = (Cv != nullptr) && (n0 >= vcol0);
    #pragma unroll
    for (int mt = 0; mt < MT; mt++)
        #pragma unroll
        for (int nt = 0; nt < NTT; nt++) {
            int row = m0 + wm + mt * 16 + g;
            int col = n0 + wn + nt * 8 + tg * 2;
            if (vblock) {
                int vc = col - vcol0;
                __half2* d0 = (__half2*)&Cv[(size_t)row * CH + vc];
                __half2* d1 = (__half2*)&Cv[(size_t)(row + 8) * CH + vc];
                *d0 = __floats2half2_rn(acc[mt][nt][0], acc[mt][nt][1]);
                *d1 = __floats2half2_rn(acc[mt][nt][2], acc[mt][nt][3]);
            } else {
                float b0v = 0.f, b1v = 0.f;
                if (bias) { b0v = __ldg(&bias[col]); b1v = __ldg(&bias[col + 1]); }
                float2* d0 = (float2*)&C[(size_t)row * N + col];
                float2* d1 = (float2*)&C[(size_t)(row + 8) * N + col];
                *d0 = make_float2(acc[mt][nt][0] + b0v, acc[mt][nt][1] + b1v);
                *d1 = make_float2(acc[mt][nt][2] + b0v, acc[mt][nt][3] + b1v);
            }
        }
}

// ---------------- local-window attention: thread-per-query, one wave ----------------
// K fp32 (stride 68 words, cp.async), V fp16 (stride 72 halves, cp.async),
// Q read directly from gmem (L2).
#define QBLK  128
#define JROWS (QBLK + 2*WIN)   // 142
#define KPAD  68               // fp32 word stride; 68%32=4 -> conflict-free phases
#define VPADH 72               // half stride (144B = 9x16B); same bank rotation
#define NWIN  (2*WIN + 1)      // 15
#define SMEM_ATTN (JROWS*KPAD*4 + JROWS*VPADH*2)   // 59072

__global__ void __launch_bounds__(128, 3)
local_attn(const float* __restrict__ qk, const __half* __restrict__ v16,
           __half* __restrict__ oatt)
{
    extern __shared__ float sm[];
    float (*ks)[KPAD] = (float(*)[KPAD])sm;
    __half* vsb = (__half*)(sm + JROWS * KPAD);
    const uint32_t sbK = smem_u32(sm);
    const uint32_t sbV = smem_u32(vsb);

    const int nblk = NSEQ / QBLK;          // 16
    const int i0 = (blockIdx.x % nblk) * QBLK;
    const int h  = (blockIdx.x / nblk) % NH;
    const int b  = blockIdx.x / (nblk * NH);

    const int tid = threadIdx.x;
    const int doff = h * DH;
    const size_t rbase = (size_t)b * NSEQ;

    const int jbase = (i0 - WIN > 0) ? i0 - WIN : 0;
    const int jend  = (i0 + QBLK - 1 + WIN < NSEQ - 1) ? i0 + QBLK - 1 + WIN : NSEQ - 1;
    const int jtot  = jend - jbase + 1;

    // stage K (fp32, 16 segs/row) and V (fp16, 8 segs/row) via cp.async
    {
        const char* kbase = (const char*)(qk + (rbase + jbase) * C2 + CH + doff);
        const char* vbase = (const char*)(v16 + (rbase + jbase) * CH + doff);
        for (int s = tid; s < jtot * 16; s += 128) {
            const int row = s >> 4, seg = s & 15;
            cp16(sbK + row * (KPAD * 4) + seg * 16, kbase + (size_t)row * (C2 * 4) + seg * 16);
        }
        for (int s = tid; s < jtot * 8; s += 128) {
            const int row = s >> 3, seg = s & 7;
            cp16(sbV + row * (VPADH * 2) + seg * 16, vbase + (size_t)row * (CH * 2) + seg * 16);
        }
        CP_COMMIT();
        CP_WAIT0();
        __syncthreads();
    }

    const int i = i0 + tid;
    const int j0 = (i - WIN > 0) ? i - WIN : 0;
    const int j1 = (i + WIN < NSEQ - 1) ? i + WIN : NSEQ - 1;
    const int nj = j1 - j0 + 1;
    const int rb = j0 - jbase;

    const float* qrow = qk + (rbase + i) * C2 + doff;

    // ---- phase A: logits ----
    float lg[NWIN];
    #pragma unroll
    for (int jj = 0; jj < NWIN; jj++) lg[jj] = 0.f;

    #pragma unroll
    for (int dc = 0; dc < 4; dc++) {
        float4 q0 = *(const float4*)(qrow + dc * 16 + 0);
        float4 q1 = *(const float4*)(qrow + dc * 16 + 4);
        float4 q2 = *(const float4*)(qrow + dc * 16 + 8);
        float4 q3 = *(const float4*)(qrow + dc * 16 + 12);
        #pragma unroll
        for (int jj = 0; jj < NWIN; jj++) {
            if (jj < nj) {
                const float* kr = &ks[rb + jj][dc * 16];
                float4 k0 = *(const float4*)(kr + 0);
                float4 k1 = *(const float4*)(kr + 4);
                float4 k2 = *(const float4*)(kr + 8);
                float4 k3 = *(const float4*)(kr + 12);
                lg[jj] += q0.x*k0.x + q0.y*k0.y + q0.z*k0.z + q0.w*k0.w
                        + q1.x*k1.x + q1.y*k1.y + q1.z*k1.z + q1.w*k1.w
                        + q2.x*k2.x + q2.y*k2.y + q2.z*k2.z + q2.w*k2.w
                        + q3.x*k3.x + q3.y*k3.y + q3.z*k3.z + q3.w*k3.w;
            }
        }
    }

    // ---- softmax ----
    const float scale = 0.125f;
    float m = -1e30f;
    #pragma unroll
    for (int jj = 0; jj < NWIN; jj++) {
        if (jj < nj) { lg[jj] *= scale; m = fmaxf(m, lg[jj]); }
    }
    float den = 0.f;
    #pragma unroll
    for (int jj = 0; jj < NWIN; jj++) {
        if (jj < nj) { lg[jj] = __expf(lg[jj] - m); den += lg[jj]; }
    }
    const float inv = 1.f / den;
    #pragma unroll
    for (int jj = 0; jj < NWIN; jj++) lg[jj] *= inv;

    // ---- phase B: output = sum p_j * v_j (V fp16 in smem) ----
    __half* orow = oatt + (rbase + i) * CH + doff;
    #pragma unroll
    for (int dc = 0; dc < 4; dc++) {
        float a[16];
        #pragma unroll
        for (int t = 0; t < 16; t++) a[t] = 0.f;
        #pragma unroll
        for (int jj = 0; jj < NWIN; jj++) {
            if (jj < nj) {
                const float p = lg[jj];
                const __half* vr = vsb + (rb + jj) * VPADH + dc * 16;
                uint4 u0 = *(const uint4*)vr;
                uint4 u1 = *(const uint4*)(vr + 8);
                const __half2* h0 = (const __half2*)&u0;
                const __half2* h1 = (const __half2*)&u1;
                #pragma unroll
                for (int t = 0; t < 4; t++) {
                    float2 f = __half22float2(h0[t]);
                    a[2*t + 0] += p * f.x;
                    a[2*t + 1] += p * f.y;
                }
                #pragma unroll
                for (int t = 0; t < 4; t++) {
                    float2 f = __half22float2(h1[t]);
                    a[8 + 2*t + 0] += p * f.x;
                    a[8 + 2*t + 1] += p * f.y;
                }
            }
        }
        __half2 hb[8];
        #pragma unroll
        for (int t = 0; t < 8; t++) hb[t] = __floats2half2_rn(a[2*t], a[2*t + 1]);
        uint4* dst = (uint4*)(orow + dc * 16);
        dst[0] = *(uint4*)&hb[0];
        dst[1] = *(uint4*)&hb[4];
    }
}

// ---------------- launch ----------------
extern "C" void kernel_launch(void* const* d_in, const int* in_sizes, int n_in,
                              void* d_out, int out_size)
{
    const float* x      = (const float*)d_in[0];
    const float* w_qkv  = (const float*)d_in[1];
    const float* w_proj = (const float*)d_in[2];
    const float* b_proj = (const float*)d_in[3];
    float* out = (float*)d_out;

    float* qk;
    __half *v16, *x16, *wq16, *wp16, *att;
    cudaGetSymbolAddress((void**)&qk,  g_qk);
    cudaGetSymbolAddress((void**)&v16, g_v16);
    cudaGetSymbolAddress((void**)&x16, g_x16);
    cudaGetSymbolAddress((void**)&wq16, g_wq16);
    cudaGetSymbolAddress((void**)&wp16, g_wp16);
    cudaGetSymbolAddress((void**)&att, g_att);

    constexpr int SMEM_QKV  = 3 * (128 * 128 + 128 * 128);   // 98304
    constexpr int SMEM_PROJ = 3 * (64 * 128 + 192 * 128);    // 98304
    cudaFuncSetAttribute((void*)gemm1<128, 128>, cudaFuncAttributeMaxDynamicSharedMemorySize, SMEM_QKV);
    cudaFuncSetAttribute((void*)gemm1<64, 192>,  cudaFuncAttributeMaxDynamicSharedMemorySize, SMEM_PROJ);
    cudaFuncSetAttribute((void*)local_attn,      cudaFuncAttributeMaxDynamicSharedMemorySize, SMEM_ATTN);

    // 1) fused conversions
    {
        const int n4 = N4_X + N4_Q + N4_P;
        conv_all<<<(n4 + 255) / 256, 256>>>(x, w_qkv, w_proj, x16, wq16, wp16);
    }
    // 2) QKV GEMM: [4096, 2304]; Q,K -> fp32 (stride 1536), V -> fp16 buffer
    {
        dim3 grid(C3 / 128, MTOT / 128);   // 18 x 32
        gemm1<128, 128><<<grid, 256, SMEM_QKV>>>(x16, wq16, nullptr, qk, C2, v16, C2);
    }
    // 3) attention -> fp16 (thread-per-query, one wave at 3 CTAs/SM)
    {
        const int blocks = BATCH * NH * (NSEQ / QBLK);  // 384
        local_attn<<<blocks, 128, SMEM_ATTN>>>(qk, v16, att);
    }
    // 4) proj GEMM: [4096, 768] + bias — 256 CTAs, one wave
    {
        dim3 grid(CH / 192, MTOT / 64);    // 4 x 64
        gemm1<64, 192><<<grid, 256, SMEM_PROJ>>>(att, wp16, b_proj, out, CH, nullptr, 0);
    }
}